// round 8
// baseline (speedup 1.0000x reference)
#include <cuda_runtime.h>
#include <cstdint>
#include <cmath>

// Problem constants
#define BB   8
#define TT   4096
#define DD   256
#define MTOT (BB*TT)        // 32768
#define KTOT 512            // 2 taps x 256
#define NSEG 64
#define SEGL (TT/NSEG)      // 64

// GEMM tiling: BM=256 (fused taps), BN=128, per-stage d-chunk of 32
#define BM 256
#define BN 128
#define NST 8               // 8 d-chunk stages (each covers BOTH taps)
#define STAGES 3
#define A_ROWS (BM+1)                   // 257 rows: tokens m0-1 .. m0+255
#define A_BYTES (A_ROWS*128)            // 32896
#define B_BYTES (2*BN*128)              // 32768 (two taps)
#define STAGE_BYTES (A_BYTES+B_BYTES)   // 65664
#define DYN_SMEM (STAGES*STAGE_BYTES)   // 196992

// ---------------- scratch (device globals) ----------------
__device__ float g_z[(size_t)MTOT*DD];
__device__ float g_f[(size_t)MTOT*DD];
__device__ float g_o[(size_t)MTOT*DD];
__device__ float g_xt[(size_t)MTOT*DD];       // x pre-rounded to tf32 (RNA)
__device__ float g_wt[3*DD*KTOT];             // Wt[g][n][k], k-major, tf32-rounded
__device__ float g_segA[BB*NSEG*DD];
__device__ float g_segB[BB*NSEG*DD];
__device__ float g_carry[BB*NSEG*DD];

// ---------------- helpers ----------------
__device__ __forceinline__ uint32_t smem_u32(const void* p) {
    uint32_t a;
    asm("{ .reg .u64 t; cvta.to.shared.u64 t, %1; cvt.u32.u64 %0, t; }" : "=r"(a) : "l"(p));
    return a;
}
__device__ __forceinline__ float tf32_rna(float x) {
    uint32_t r;
    asm("cvt.rna.tf32.f32 %0, %1;" : "=r"(r) : "f"(x));
    return __uint_as_float(r);
}
__device__ __forceinline__ void cp_async16(uint32_t dst, const void* src, uint32_t src_bytes) {
    asm volatile("cp.async.cg.shared.global [%0], [%1], 16, %2;"
                 :: "r"(dst), "l"(src), "r"(src_bytes) : "memory");
}
__device__ __forceinline__ void cp_commit() {
    asm volatile("cp.async.commit_group;" ::: "memory");
}
template<int N> __device__ __forceinline__ void cp_wait() {
    asm volatile("cp.async.wait_group %0;" :: "n"(N) : "memory");
}
__device__ __forceinline__ void ldsm4(uint32_t& r0, uint32_t& r1, uint32_t& r2, uint32_t& r3,
                                      uint32_t addr) {
    asm volatile("ldmatrix.sync.aligned.m8n8.x4.shared.b16 {%0,%1,%2,%3}, [%4];"
                 : "=r"(r0), "=r"(r1), "=r"(r2), "=r"(r3) : "r"(addr));
}
__device__ __forceinline__ void mma_tf32(float c[4], const uint32_t a[4], const uint32_t b[2]) {
    asm("mma.sync.aligned.m16n8k8.row.col.f32.tf32.tf32.f32 "
        "{%0,%1,%2,%3}, {%4,%5,%6,%7}, {%8,%9}, {%0,%1,%2,%3};"
        : "+f"(c[0]), "+f"(c[1]), "+f"(c[2]), "+f"(c[3])
        : "r"(a[0]), "r"(a[1]), "r"(a[2]), "r"(a[3]), "r"(b[0]), "r"(b[1]));
}

// ---------------- prep kernels ----------------
__global__ void cvt_x(const float* __restrict__ x) {
    size_t i = (size_t)blockIdx.x * 256 + threadIdx.x;   // over float4s
    float4 v = ((const float4*)x)[i];
    v.x = tf32_rna(v.x); v.y = tf32_rna(v.y); v.z = tf32_rna(v.z); v.w = tf32_rna(v.w);
    ((float4*)g_xt)[i] = v;
}

__global__ void trans_w(const float* __restrict__ Wz, const float* __restrict__ Wf,
                        const float* __restrict__ Wo) {
    __shared__ float t[32][33];
    int g = blockIdx.z, tap = blockIdx.y;
    const float* W = (g == 0) ? Wz : (g == 1) ? Wf : Wo;
    int d0 = (blockIdx.x & 7) * 32;
    int n0 = (blockIdx.x >> 3) * 32;
    #pragma unroll
    for (int r = 0; r < 4; r++) {
        int d = d0 + threadIdx.y + r * 8;
        t[threadIdx.y + r * 8][threadIdx.x] =
            tf32_rna(W[(size_t)tap * 65536 + (size_t)d * 256 + n0 + threadIdx.x]);
    }
    __syncthreads();
    #pragma unroll
    for (int r = 0; r < 4; r++) {
        int n = n0 + threadIdx.y + r * 8;
        g_wt[(size_t)g * (DD * KTOT) + (size_t)n * KTOT + tap * 256 + d0 + threadIdx.x] =
            t[threadIdx.x][threadIdx.y + r * 8];
    }
}

// ---------------- mma.sync tf32 gate GEMM (fused taps) ----------------
// BM=256, BN=128. A smem holds tokens m0-1..m0+255 once per d-chunk; both conv
// taps read it at row offsets 0 / +1. 512 threads = 16 warps (4m x 4n),
// warp tile 64x32, m16n8k8, 3-stage cp.async pipeline.
__global__ __launch_bounds__(512)
void gates_gemm(const float* __restrict__ bz, const float* __restrict__ bfv,
                const float* __restrict__ bo) {
    extern __shared__ char dyn[];
    const uint32_t sbase = smem_u32(dyn);

    const int tid  = threadIdx.x;
    const int warp = tid >> 5, lane = tid & 31;
    const int gq = lane >> 2, q = lane & 3;
    const int wm0 = (warp >> 2) * 64;
    const int wn0 = (warp & 3) * 32;

    const int n0   = blockIdx.x * BN;      // n fast -> A reuse in L2 within a wave
    const int m0   = blockIdx.y * BM;
    const int gate = n0 >> 8;
    const int n0g  = n0 & 255;
    const bool first_blk = ((m0 & (TT - 1)) == 0);

    const float* bias = (gate == 0) ? bz : (gate == 1) ? bfv : bo;
    float* dst        = (gate == 0) ? g_z : (gate == 1) ? g_f : g_o;
    const float* Wb   = g_wt + (size_t)gate * (DD * KTOT) + (size_t)n0g * KTOT;

    float acc[4][4][4];
    #pragma unroll
    for (int mt = 0; mt < 4; mt++)
        #pragma unroll
        for (int nt = 0; nt < 4; nt++)
            #pragma unroll
            for (int i = 0; i < 4; i++) acc[mt][nt][i] = 0.0f;

    // ---- producer: stage kb covers d-chunk d0=kb*32 for A once + B both taps ----
    auto issue_stage = [&](int kb, int st) {
        const uint32_t abase = sbase + st * STAGE_BYTES;
        const uint32_t bbase = abase + A_BYTES;
        const int d0 = kb << 5;
        // A: 257 rows x 8 chunks = 2056 16B-chunks
        for (int idx = tid; idx < A_ROWS * 8; idx += 512) {
            int row = idx >> 3, k4 = idx & 7;
            uint32_t sw = (uint32_t)(row << 7) + (uint32_t)((k4 ^ (row & 7)) << 4);
            int m = m0 - 1 + row;                 // token for this smem row
            uint32_t nb = 16;
            const float* src = g_xt + (size_t)m * DD + d0 + (k4 << 2);
            if (row == 0 && first_blk) { nb = 0; src = g_xt; }
            cp_async16(abase + sw, src, nb);
        }
        // B: 2 taps x 128 rows x 8 chunks = 2048 chunks (exactly 4 per thread)
        #pragma unroll
        for (int p = 0; p < 4; p++) {
            int idx = tid + p * 512;
            int tap = idx >> 10;
            int rem = idx & 1023;
            int row = rem >> 3, k4 = rem & 7;
            uint32_t sw = (uint32_t)(tap << 14) + (uint32_t)(row << 7) +
                          (uint32_t)((k4 ^ (row & 7)) << 4);
            const float* src = Wb + (size_t)row * KTOT + tap * 256 + d0 + (k4 << 2);
            cp_async16(bbase + sw, src, 16);
        }
    };

    // ---- consumer ----
    const int mi1 = (lane >> 3) & 1;
    const int mi2 = lane >> 4;
    const int rr  = lane & 7;
    auto compute = [&](int st) {
        const uint32_t ab = sbase + st * STAGE_BYTES;
        const uint32_t bb = ab + A_BYTES;
        #pragma unroll
        for (int tap = 0; tap < 2; tap++) {
            #pragma unroll
            for (int ks = 0; ks < 4; ks++) {
                uint32_t af[4][4], bf[4][2];
                #pragma unroll
                for (int mt = 0; mt < 4; mt++) {
                    int row = wm0 + mt * 16 + mi1 * 8 + rr + tap;   // +1 row = next token
                    int k4  = ks * 2 + mi2;
                    uint32_t addr = ab + (row << 7) + ((k4 ^ (row & 7)) << 4);
                    ldsm4(af[mt][0], af[mt][1], af[mt][2], af[mt][3], addr);
                }
                #pragma unroll
                for (int ntp = 0; ntp < 2; ntp++) {
                    int row = wn0 + ntp * 16 + mi2 * 8 + rr;
                    int k4  = ks * 2 + mi1;
                    uint32_t addr = bb + (tap << 14) + (row << 7) + ((k4 ^ (row & 7)) << 4);
                    uint32_t r0, r1, r2, r3;
                    ldsm4(r0, r1, r2, r3, addr);
                    bf[2*ntp][0] = r0; bf[2*ntp][1] = r1;
                    bf[2*ntp+1][0] = r2; bf[2*ntp+1][1] = r3;
                }
                #pragma unroll
                for (int mt = 0; mt < 4; mt++)
                    #pragma unroll
                    for (int nt = 0; nt < 4; nt++)
                        mma_tf32(acc[mt][nt], af[mt], bf[nt]);
            }
        }
    };

    // ---- pipeline: 8 stages, 3 buffers ----
    issue_stage(0, 0); cp_commit();
    issue_stage(1, 1); cp_commit();

    int st = 0;
    for (int kb = 0; kb < NST; kb++) {
        cp_wait<1>();
        __syncthreads();
        if (kb + 2 < NST) issue_stage(kb + 2, (kb + 2) % STAGES);
        cp_commit();
        compute(st);
        st = (st + 1 == STAGES) ? 0 : st + 1;
        if (kb + 1 < NST) __syncthreads();   // all warps done with buffer before reuse window
    }

    // ---- epilogue: bias + activation, float2 stores ----
    #pragma unroll
    for (int mt = 0; mt < 4; mt++) {
        #pragma unroll
        for (int nt = 0; nt < 4; nt++) {
            #pragma unroll
            for (int h = 0; h < 2; h++) {
                int m  = m0 + wm0 + mt * 16 + gq + h * 8;
                int n  = n0g + wn0 + nt * 8 + q * 2;
                float v0 = acc[mt][nt][2*h]   + bias[n];
                float v1 = acc[mt][nt][2*h+1] + bias[n + 1];
                if (gate == 0) { v0 = tanhf(v0); v1 = tanhf(v1); }
                else { v0 = 1.0f / (1.0f + expf(-v0)); v1 = 1.0f / (1.0f + expf(-v1)); }
                *(float2*)(dst + (size_t)m * DD + n) = make_float2(v0, v1);
            }
        }
    }
}

// ---------------- segmented scan (float4-vectorized) ----------------
__global__ void seg_reduce() {
    int tid = blockIdx.x * 256 + threadIdx.x;   // 32768 threads: (b, s, d4)
    int d4 = tid & 63;
    int s  = (tid >> 6) & (NSEG - 1);
    int b  = tid >> 12;
    size_t base4 = (((size_t)b * TT + (size_t)s * SEGL) * DD) / 4 + d4;
    float4 A = make_float4(1.f, 1.f, 1.f, 1.f);
    float4 Bv = make_float4(0.f, 0.f, 0.f, 0.f);
    #pragma unroll 4
    for (int i = 0; i < SEGL; i++) {
        float4 f = ((const float4*)g_f)[base4 + (size_t)i * (DD/4)];
        float4 z = ((const float4*)g_z)[base4 + (size_t)i * (DD/4)];
        A.x *= f.x; A.y *= f.y; A.z *= f.z; A.w *= f.w;
        Bv.x = f.x * Bv.x + (1.0f - f.x) * z.x;
        Bv.y = f.y * Bv.y + (1.0f - f.y) * z.y;
        Bv.z = f.z * Bv.z + (1.0f - f.z) * z.z;
        Bv.w = f.w * Bv.w + (1.0f - f.w) * z.w;
    }
    int sidx = (b * NSEG + s) * (DD/4) + d4;
    ((float4*)g_segA)[sidx] = A;
    ((float4*)g_segB)[sidx] = Bv;
}

__global__ void seg_carry() {
    int tid = blockIdx.x * 256 + threadIdx.x;   // 512 threads: (b, d4)
    int d4 = tid & 63;
    int b  = tid >> 6;
    float4 c = make_float4(0.f, 0.f, 0.f, 0.f);
    for (int s = 0; s < NSEG; s++) {
        int idx = (b * NSEG + s) * (DD/4) + d4;
        ((float4*)g_carry)[idx] = c;
        float4 A = ((const float4*)g_segA)[idx];
        float4 Bv = ((const float4*)g_segB)[idx];
        c.x = A.x * c.x + Bv.x;
        c.y = A.y * c.y + Bv.y;
        c.z = A.z * c.z + Bv.z;
        c.w = A.w * c.w + Bv.w;
    }
}

__global__ void seg_apply(float* __restrict__ out) {
    int tid = blockIdx.x * 256 + threadIdx.x;   // 32768 threads
    int d4 = tid & 63;
    int s  = (tid >> 6) & (NSEG - 1);
    int b  = tid >> 12;
    size_t base4 = (((size_t)b * TT + (size_t)s * SEGL) * DD) / 4 + d4;
    float4 c = ((const float4*)g_carry)[(b * NSEG + s) * (DD/4) + d4];
    #pragma unroll 4
    for (int i = 0; i < SEGL; i++) {
        size_t idx = base4 + (size_t)i * (DD/4);
        float4 f = ((const float4*)g_f)[idx];
        float4 z = ((const float4*)g_z)[idx];
        float4 o = ((const float4*)g_o)[idx];
        c.x = f.x * c.x + (1.0f - f.x) * z.x;
        c.y = f.y * c.y + (1.0f - f.y) * z.y;
        c.z = f.z * c.z + (1.0f - f.z) * z.z;
        c.w = f.w * c.w + (1.0f - f.w) * z.w;
        float4 h = make_float4(o.x * c.x, o.y * c.y, o.z * c.z, o.w * c.w);
        ((float4*)out)[idx] = h;
    }
}

// ---------------- launch ----------------
extern "C" void kernel_launch(void* const* d_in, const int* in_sizes, int n_in,
                              void* d_out, int out_size) {
    const float* x   = (const float*)d_in[0];
    const float* Wz  = (const float*)d_in[1];
    const float* Wf  = (const float*)d_in[2];
    const float* Wo  = (const float*)d_in[3];
    const float* bz  = (const float*)d_in[4];
    const float* bfv = (const float*)d_in[5];
    const float* bo  = (const float*)d_in[6];
    float* out = (float*)d_out;

    cudaFuncSetAttribute(gates_gemm, cudaFuncAttributeMaxDynamicSharedMemorySize, DYN_SMEM);

    cvt_x<<<(MTOT * DD / 4) / 256, 256>>>(x);
    trans_w<<<dim3(64, 2, 3), dim3(32, 8)>>>(Wz, Wf, Wo);
    gates_gemm<<<dim3(768 / BN, MTOT / BM), 512, DYN_SMEM>>>(bz, bfv, bo);
    seg_reduce<<<(BB * NSEG * DD / 4) / 256, 256>>>();
    seg_carry<<<(BB * DD / 4) / 256, 256>>>();
    seg_apply<<<(BB * NSEG * DD / 4) / 256, 256>>>(out);
}

// round 10
// speedup vs baseline: 1.0554x; 1.0554x over previous
#include <cuda_runtime.h>
#include <cuda.h>
#include <cstdint>
#include <cmath>

// Problem constants
#define BB   8
#define TT   4096
#define DD   256
#define MTOT (BB*TT)        // 32768
#define KTOT 512            // 2 taps x 256
#define NSEG 64
#define SEGL (TT/NSEG)      // 64

// GEMM tiling: BM=128 tokens (fused taps -> 129 A rows), BN=256 (whole gate)
#define BM 128
#define BN 256
#define NST 8               // 8 d-chunk stages of 32 floats, each covers both taps
#define A_PAD   17408       // 129*128=16512 padded to 1024-mult
#define B_TAP   32768       // 256 rows * 128B
#define B_SZ    (2*B_TAP)   // 65536
#define STAGE_TX (16512 + B_SZ)              // 82048 bytes delivered per stage
#define DYN_SMEM (2*A_PAD + 2*B_SZ + 1024)   // + 1024 alignment slack (TMA SW128 needs 1024-aligned base)

// ---------------- scratch (device globals) ----------------
__device__ float g_z[(size_t)MTOT*DD];
__device__ float g_f[(size_t)MTOT*DD];
__device__ float g_o[(size_t)MTOT*DD];
__device__ float g_xt[(size_t)MTOT*DD];       // x pre-rounded to tf32 (RNA)
__device__ float g_wt[3*DD*KTOT];             // Wt[g][n][k], k-major, tf32-rounded
__device__ float g_segA[BB*NSEG*DD];
__device__ float g_segB[BB*NSEG*DD];
__device__ float g_carry[BB*NSEG*DD];

// ---------------- helpers ----------------
__device__ __forceinline__ uint32_t smem_u32(const void* p) {
    uint32_t a;
    asm("{ .reg .u64 t; cvta.to.shared.u64 t, %1; cvt.u32.u64 %0, t; }" : "=r"(a) : "l"(p));
    return a;
}
__device__ __forceinline__ float tf32_rna(float x) {
    uint32_t r;
    asm("cvt.rna.tf32.f32 %0, %1;" : "=r"(r) : "f"(x));
    return __uint_as_float(r);
}
__device__ __forceinline__ void ldsm4(uint32_t& r0, uint32_t& r1, uint32_t& r2, uint32_t& r3,
                                      uint32_t addr) {
    asm volatile("ldmatrix.sync.aligned.m8n8.x4.shared.b16 {%0,%1,%2,%3}, [%4];"
                 : "=r"(r0), "=r"(r1), "=r"(r2), "=r"(r3) : "r"(addr));
}
__device__ __forceinline__ void mma_tf32(float c[4], const uint32_t a[4], const uint32_t b[2]) {
    asm("mma.sync.aligned.m16n8k8.row.col.f32.tf32.tf32.f32 "
        "{%0,%1,%2,%3}, {%4,%5,%6,%7}, {%8,%9}, {%0,%1,%2,%3};"
        : "+f"(c[0]), "+f"(c[1]), "+f"(c[2]), "+f"(c[3])
        : "r"(a[0]), "r"(a[1]), "r"(a[2]), "r"(a[3]), "r"(b[0]), "r"(b[1]));
}
__device__ __forceinline__ void tma_load_2d(uint32_t dst, const void* map, int x, int y,
                                            uint32_t mbar) {
    asm volatile(
        "cp.async.bulk.tensor.2d.shared::cta.global.tile.mbarrier::complete_tx::bytes "
        "[%0], [%1, {%2, %3}], [%4];"
        :: "r"(dst), "l"(map), "r"(x), "r"(y), "r"(mbar) : "memory");
}
#define MBARRIER_INIT(addr, cnt) \
    asm volatile("mbarrier.init.shared.b64 [%0], %1;" :: "r"(addr), "r"(cnt) : "memory")
#define MBARRIER_EXPECT_TX(addr, bytes) \
    asm volatile("mbarrier.arrive.expect_tx.shared.b64 _, [%0], %1;" \
                 :: "r"(addr), "r"(bytes) : "memory")
#define FENCE_PROXY_ASYNC() \
    asm volatile("fence.proxy.async.shared::cta;" ::: "memory")
#define MBARRIER_WAIT_PARITY(addr, par) do {                                     \
    uint32_t _m = (addr), _p = (par), _done;                                     \
    asm volatile("{ .reg .pred p; mbarrier.try_wait.parity.acquire.cta.shared::cta.b64 p, [%1], %2;" \
                 " selp.b32 %0, 1, 0, p; }" : "=r"(_done) : "r"(_m), "r"(_p) : "memory"); \
    if (!_done) {                                                                \
        asm volatile("{ .reg .pred P1; WL%=:"                                    \
                     " mbarrier.try_wait.parity.acquire.cta.shared::cta.b64 P1, [%0], %1, 0x989680;" \
                     " @P1 bra.uni WD%=; bra.uni WL%=; WD%=: }"                  \
                     :: "r"(_m), "r"(_p) : "memory");                            \
    } } while (0)

// ---------------- prep kernels ----------------
__global__ void cvt_x(const float* __restrict__ x) {
    size_t i = (size_t)blockIdx.x * 256 + threadIdx.x;
    float4 v = ((const float4*)x)[i];
    v.x = tf32_rna(v.x); v.y = tf32_rna(v.y); v.z = tf32_rna(v.z); v.w = tf32_rna(v.w);
    ((float4*)g_xt)[i] = v;
}

__global__ void trans_w(const float* __restrict__ Wz, const float* __restrict__ Wf,
                        const float* __restrict__ Wo) {
    __shared__ float t[32][33];
    int g = blockIdx.z, tap = blockIdx.y;
    const float* W = (g == 0) ? Wz : (g == 1) ? Wf : Wo;
    int d0 = (blockIdx.x & 7) * 32;
    int n0 = (blockIdx.x >> 3) * 32;
    #pragma unroll
    for (int r = 0; r < 4; r++) {
        int d = d0 + threadIdx.y + r * 8;
        t[threadIdx.y + r * 8][threadIdx.x] =
            tf32_rna(W[(size_t)tap * 65536 + (size_t)d * 256 + n0 + threadIdx.x]);
    }
    __syncthreads();
    #pragma unroll
    for (int r = 0; r < 4; r++) {
        int n = n0 + threadIdx.y + r * 8;
        g_wt[(size_t)g * (DD * KTOT) + (size_t)n * KTOT + tap * 256 + d0 + threadIdx.x] =
            t[threadIdx.x][threadIdx.y + r * 8];
    }
}

// ---------------- TMA-fed mma.sync tf32 gate GEMM ----------------
// 256 threads = 8 warps (2m x 4n), warp tile 64x64 of m16n8k8.
// Stage = d-chunk of 32 floats: A once (129 rows incl. prev token), B both taps.
__global__ __launch_bounds__(256)
void gates_gemm(const __grid_constant__ CUtensorMap tma_a,
                const __grid_constant__ CUtensorMap tma_b,
                const float* __restrict__ bz, const float* __restrict__ bfv,
                const float* __restrict__ bo) {
    extern __shared__ char dyn[];
    __shared__ __align__(8) uint64_t s_mbar[2];
    const uint32_t sbase = (smem_u32(dyn) + 1023u) & ~1023u;   // FIX: 1024-align for SW128 TMA
    const uint32_t mb[2] = { smem_u32(&s_mbar[0]), smem_u32(&s_mbar[1]) };

    const int tid  = threadIdx.x;
    const int warp = tid >> 5, lane = tid & 31;
    const int gq = lane >> 2, q = lane & 3;
    const int wm0 = (warp >> 2) * 64;
    const int wn0 = (warp & 3) * 64;

    const int gate = blockIdx.x;           // n fast: 3 gates share A tile in L2
    const int m0   = blockIdx.y * BM;
    const bool first_blk = ((m0 & (TT - 1)) == 0);

    const float* bias = (gate == 0) ? bz : (gate == 1) ? bfv : bo;
    float* dst        = (gate == 0) ? g_z : (gate == 1) ? g_f : g_o;

    if (tid == 0) { MBARRIER_INIT(mb[0], 1); MBARRIER_INIT(mb[1], 1); }
    __syncthreads();

    float acc[4][8][4];
    #pragma unroll
    for (int mt = 0; mt < 4; mt++)
        #pragma unroll
        for (int nt = 0; nt < 8; nt++)
            #pragma unroll
            for (int i = 0; i < 4; i++) acc[mt][nt][i] = 0.0f;

    auto issue_stage = [&](int kb, int buf) {   // tid 0 only
        MBARRIER_EXPECT_TX(mb[buf], STAGE_TX);
        const int d0 = kb << 5;
        tma_load_2d(sbase + buf * A_PAD, &tma_a, d0, m0 - 1, mb[buf]);
        const uint32_t bdst = sbase + 2 * A_PAD + buf * B_SZ;
        tma_load_2d(bdst,         &tma_b, d0,       gate * 256, mb[buf]);
        tma_load_2d(bdst + B_TAP, &tma_b, 256 + d0, gate * 256, mb[buf]);
    };

    const int mi1 = (lane >> 3) & 1;
    const int mi2 = lane >> 4;
    const int rr  = lane & 7;
    auto compute = [&](int buf) {
        const uint32_t ab = sbase + buf * A_PAD;
        const uint32_t bb = sbase + 2 * A_PAD + buf * B_SZ;
        #pragma unroll
        for (int tap = 0; tap < 2; tap++) {
            #pragma unroll
            for (int ks = 0; ks < 4; ks++) {
                uint32_t af[4][4], bf[8][2];
                #pragma unroll
                for (int mt = 0; mt < 4; mt++) {
                    int row = wm0 + mt * 16 + mi1 * 8 + rr + tap;   // +1 row = next token
                    int k4  = ks * 2 + mi2;
                    uint32_t addr = ab + (row << 7) + ((k4 ^ (row & 7)) << 4);
                    ldsm4(af[mt][0], af[mt][1], af[mt][2], af[mt][3], addr);
                }
                #pragma unroll
                for (int ntp = 0; ntp < 4; ntp++) {
                    int row = wn0 + ntp * 16 + mi2 * 8 + rr;
                    int k4  = ks * 2 + mi1;
                    uint32_t addr = bb + (tap << 15) + (row << 7) + ((k4 ^ (row & 7)) << 4);
                    uint32_t r0, r1, r2, r3;
                    ldsm4(r0, r1, r2, r3, addr);
                    bf[2*ntp][0] = r0;   bf[2*ntp][1] = r1;
                    bf[2*ntp+1][0] = r2; bf[2*ntp+1][1] = r3;
                }
                #pragma unroll
                for (int mt = 0; mt < 4; mt++)
                    #pragma unroll
                    for (int nt = 0; nt < 8; nt++)
                        mma_tf32(acc[mt][nt], af[mt], bf[nt]);
            }
        }
    };

    if (tid == 0) {
        FENCE_PROXY_ASYNC();          // order mbarrier init (generic) before TMA (async)
        issue_stage(0, 0);
        issue_stage(1, 1);
    }

    for (int kb = 0; kb < NST; kb++) {
        const int buf = kb & 1;
        MBARRIER_WAIT_PARITY(mb[buf], (kb >> 1) & 1);
        if (first_blk) {
            // token m0-1 belongs to previous batch (or m0==0): tap-0 row must be zero
            if (tid < 8) {
                const uint32_t a0 = sbase + buf * A_PAD + (tid << 4);  // row0: swizzle=identity
                asm volatile("st.shared.v4.b32 [%0], {%1,%1,%1,%1};" :: "r"(a0), "r"(0) : "memory");
            }
            __syncthreads();
        }
        compute(buf);
        __syncthreads();
        if (tid == 0 && kb + 2 < NST) {
            FENCE_PROXY_ASYNC();      // order generic smem writes before async-proxy reuse
            issue_stage(kb + 2, buf);
        }
    }

    // ---- epilogue: bias + activation, float2 stores ----
    #pragma unroll
    for (int mt = 0; mt < 4; mt++) {
        #pragma unroll
        for (int nt = 0; nt < 8; nt++) {
            #pragma unroll
            for (int h = 0; h < 2; h++) {
                int m = m0 + wm0 + mt * 16 + gq + h * 8;
                int n = wn0 + nt * 8 + q * 2;
                float v0 = acc[mt][nt][2*h]   + bias[n];
                float v1 = acc[mt][nt][2*h+1] + bias[n + 1];
                if (gate == 0) { v0 = tanhf(v0); v1 = tanhf(v1); }
                else { v0 = 1.0f / (1.0f + expf(-v0)); v1 = 1.0f / (1.0f + expf(-v1)); }
                *(float2*)(dst + (size_t)m * DD + n) = make_float2(v0, v1);
            }
        }
    }
}

// ---------------- segmented scan: float2, 65536 threads ----------------
__global__ void seg_reduce() {
    int tid = blockIdx.x * 256 + threadIdx.x;   // 65536 threads: (b, s, d2)
    int d2 = tid & 127;
    int s  = (tid >> 7) & (NSEG - 1);
    int b  = tid >> 13;
    size_t base2 = (((size_t)b * TT + (size_t)s * SEGL) * DD) / 2 + d2;
    float2 A = make_float2(1.f, 1.f);
    float2 Bv = make_float2(0.f, 0.f);
    #pragma unroll 4
    for (int i = 0; i < SEGL; i++) {
        float2 f = ((const float2*)g_f)[base2 + (size_t)i * (DD/2)];
        float2 z = ((const float2*)g_z)[base2 + (size_t)i * (DD/2)];
        A.x *= f.x; A.y *= f.y;
        Bv.x = f.x * Bv.x + (1.0f - f.x) * z.x;
        Bv.y = f.y * Bv.y + (1.0f - f.y) * z.y;
    }
    int sidx = (b * NSEG + s) * (DD/2) + d2;
    ((float2*)g_segA)[sidx] = A;
    ((float2*)g_segB)[sidx] = Bv;
}

__global__ void seg_carry() {
    int tid = blockIdx.x * 256 + threadIdx.x;   // 1024 threads: (b, d2)
    int d2 = tid & 127;
    int b  = tid >> 7;
    float2 c = make_float2(0.f, 0.f);
    for (int s = 0; s < NSEG; s++) {
        int idx = (b * NSEG + s) * (DD/2) + d2;
        ((float2*)g_carry)[idx] = c;
        float2 A = ((const float2*)g_segA)[idx];
        float2 Bv = ((const float2*)g_segB)[idx];
        c.x = A.x * c.x + Bv.x;
        c.y = A.y * c.y + Bv.y;
    }
}

__global__ void seg_apply(float* __restrict__ out) {
    int tid = blockIdx.x * 256 + threadIdx.x;   // 65536 threads
    int d2 = tid & 127;
    int s  = (tid >> 7) & (NSEG - 1);
    int b  = tid >> 13;
    size_t base2 = (((size_t)b * TT + (size_t)s * SEGL) * DD) / 2 + d2;
    float2 c = ((const float2*)g_carry)[(b * NSEG + s) * (DD/2) + d2];
    #pragma unroll 4
    for (int i = 0; i < SEGL; i++) {
        size_t idx = base2 + (size_t)i * (DD/2);
        float2 f = ((const float2*)g_f)[idx];
        float2 z = ((const float2*)g_z)[idx];
        float2 o = ((const float2*)g_o)[idx];
        c.x = f.x * c.x + (1.0f - f.x) * z.x;
        c.y = f.y * c.y + (1.0f - f.y) * z.y;
        ((float2*)out)[idx] = make_float2(o.x * c.x, o.y * c.y);
    }
}

// ---------------- launch ----------------
typedef CUresult (*EncodeFn)(CUtensorMap*, CUtensorMapDataType, cuuint32_t, void*,
                             const cuuint64_t*, const cuuint64_t*, const cuuint32_t*,
                             const cuuint32_t*, CUtensorMapInterleave, CUtensorMapSwizzle,
                             CUtensorMapL2promotion, CUtensorMapFloatOOBfill);

extern "C" void kernel_launch(void* const* d_in, const int* in_sizes, int n_in,
                              void* d_out, int out_size) {
    const float* x   = (const float*)d_in[0];
    const float* Wz  = (const float*)d_in[1];
    const float* Wf  = (const float*)d_in[2];
    const float* Wo  = (const float*)d_in[3];
    const float* bz  = (const float*)d_in[4];
    const float* bfv = (const float*)d_in[5];
    const float* bo  = (const float*)d_in[6];
    float* out = (float*)d_out;

    // encode tensormaps (host-side, capture-safe, deterministic every call)
    void* encode_fn = nullptr;
    cudaDriverEntryPointQueryResult qr;
    cudaGetDriverEntryPointByVersion("cuTensorMapEncodeTiled", &encode_fn, 12000,
                                     cudaEnableDefault, &qr);
    void *xa = nullptr, *wa = nullptr;
    cudaGetSymbolAddress(&xa, g_xt);
    cudaGetSymbolAddress(&wa, g_wt);

    CUtensorMap tmap_a, tmap_b;
    {
        cuuint64_t dims[2]    = { 256, 32768 };          // {cols, rows}
        cuuint64_t strides[1] = { 256 * 4 };
        cuuint32_t box[2]     = { 32, 129 };             // d-chunk x (BM+1 rows)
        cuuint32_t es[2]      = { 1, 1 };
        ((EncodeFn)encode_fn)(&tmap_a, CU_TENSOR_MAP_DATA_TYPE_FLOAT32, 2, xa,
                              dims, strides, box, es,
                              CU_TENSOR_MAP_INTERLEAVE_NONE, CU_TENSOR_MAP_SWIZZLE_128B,
                              CU_TENSOR_MAP_L2_PROMOTION_L2_128B,
                              CU_TENSOR_MAP_FLOAT_OOB_FILL_NONE);
    }
    {
        cuuint64_t dims[2]    = { 512, 768 };            // {k-cols, 3*256 n-rows}
        cuuint64_t strides[1] = { 512 * 4 };
        cuuint32_t box[2]     = { 32, 256 };             // d-chunk x BN rows
        cuuint32_t es[2]      = { 1, 1 };
        ((EncodeFn)encode_fn)(&tmap_b, CU_TENSOR_MAP_DATA_TYPE_FLOAT32, 2, wa,
                              dims, strides, box, es,
                              CU_TENSOR_MAP_INTERLEAVE_NONE, CU_TENSOR_MAP_SWIZZLE_128B,
                              CU_TENSOR_MAP_L2_PROMOTION_L2_128B,
                              CU_TENSOR_MAP_FLOAT_OOB_FILL_NONE);
    }

    cudaFuncSetAttribute(gates_gemm, cudaFuncAttributeMaxDynamicSharedMemorySize, DYN_SMEM);

    cvt_x<<<(MTOT * DD / 4) / 256, 256>>>(x);
    trans_w<<<dim3(64, 2, 3), dim3(32, 8)>>>(Wz, Wf, Wo);
    gates_gemm<<<dim3(3, MTOT / BM), 256, DYN_SMEM>>>(tmap_a, tmap_b, bz, bfv, bo);
    seg_reduce<<<(BB * NSEG * DD / 2) / 256, 256>>>();
    seg_carry<<<(BB * DD / 2) / 256, 256>>>();
    seg_apply<<<(BB * NSEG * DD / 2) / 256, 256>>>(out);
}

// round 11
// speedup vs baseline: 1.7639x; 1.6713x over previous
#include <cuda_runtime.h>
#include <cuda_fp16.h>
#include <cstdint>
#include <cmath>

// Problem constants
#define BB   8
#define TT   4096
#define DD   256
#define MTOT (BB*TT)        // 32768
#define KTOT 512            // 2 taps x 256
#define NSEG 64
#define SEGL (TT/NSEG)      // 64

// GEMM tiling: fp16, BK=64 halves (128B rows)
#define BM 128
#define BN 128
#define BK 64
#define NKB (KTOT/BK)       // 8
#define STAGES 3
#define A_BYTES (BM*128)            // 16384
#define B_BYTES (BN*128)            // 16384
#define STAGE_BYTES (A_BYTES+B_BYTES)
#define DYN_SMEM (STAGES*STAGE_BYTES)   // 98304

// ---------------- scratch (device globals) ----------------
__device__ float  g_z[(size_t)MTOT*DD];
__device__ float  g_f[(size_t)MTOT*DD];
__device__ float  g_o[(size_t)MTOT*DD];
__device__ __half g_xh[(size_t)MTOT*DD];      // x in fp16 (RN)
__device__ __half g_wh[3*DD*KTOT];            // Wt[g][n][k], k-major, fp16
__device__ float  g_segA[BB*NSEG*DD];
__device__ float  g_segB[BB*NSEG*DD];
__device__ float  g_carry[BB*NSEG*DD];

// ---------------- helpers ----------------
__device__ __forceinline__ uint32_t smem_u32(const void* p) {
    uint32_t a;
    asm("{ .reg .u64 t; cvta.to.shared.u64 t, %1; cvt.u32.u64 %0, t; }" : "=r"(a) : "l"(p));
    return a;
}
__device__ __forceinline__ void cp_async16(uint32_t dst, const void* src, uint32_t src_bytes) {
    asm volatile("cp.async.cg.shared.global [%0], [%1], 16, %2;"
                 :: "r"(dst), "l"(src), "r"(src_bytes) : "memory");
}
__device__ __forceinline__ void cp_commit() {
    asm volatile("cp.async.commit_group;" ::: "memory");
}
template<int N> __device__ __forceinline__ void cp_wait() {
    asm volatile("cp.async.wait_group %0;" :: "n"(N) : "memory");
}
__device__ __forceinline__ void ldsm4(uint32_t& r0, uint32_t& r1, uint32_t& r2, uint32_t& r3,
                                      uint32_t addr) {
    asm volatile("ldmatrix.sync.aligned.m8n8.x4.shared.b16 {%0,%1,%2,%3}, [%4];"
                 : "=r"(r0), "=r"(r1), "=r"(r2), "=r"(r3) : "r"(addr));
}
__device__ __forceinline__ void mma_f16(float c[4], const uint32_t a[4], const uint32_t b[2]) {
    asm("mma.sync.aligned.m16n8k16.row.col.f32.f16.f16.f32 "
        "{%0,%1,%2,%3}, {%4,%5,%6,%7}, {%8,%9}, {%0,%1,%2,%3};"
        : "+f"(c[0]), "+f"(c[1]), "+f"(c[2]), "+f"(c[3])
        : "r"(a[0]), "r"(a[1]), "r"(a[2]), "r"(a[3]), "r"(b[0]), "r"(b[1]));
}

// ---------------- prep kernels ----------------
__global__ void cvt_x(const float* __restrict__ x) {
    size_t i = (size_t)blockIdx.x * 256 + threadIdx.x;   // over float4s
    float4 v = ((const float4*)x)[i];
    __half2 lo = __floats2half2_rn(v.x, v.y);
    __half2 hi = __floats2half2_rn(v.z, v.w);
    ((__half2*)g_xh)[i * 2]     = lo;
    ((__half2*)g_xh)[i * 2 + 1] = hi;
}

__global__ void trans_w(const float* __restrict__ Wz, const float* __restrict__ Wf,
                        const float* __restrict__ Wo) {
    __shared__ float t[32][33];
    int g = blockIdx.z, tap = blockIdx.y;
    const float* W = (g == 0) ? Wz : (g == 1) ? Wf : Wo;
    int d0 = (blockIdx.x & 7) * 32;
    int n0 = (blockIdx.x >> 3) * 32;
    #pragma unroll
    for (int r = 0; r < 4; r++) {
        int d = d0 + threadIdx.y + r * 8;
        t[threadIdx.y + r * 8][threadIdx.x] =
            W[(size_t)tap * 65536 + (size_t)d * 256 + n0 + threadIdx.x];
    }
    __syncthreads();
    #pragma unroll
    for (int r = 0; r < 4; r++) {
        int n = n0 + threadIdx.y + r * 8;
        g_wh[(size_t)g * (DD * KTOT) + (size_t)n * KTOT + tap * 256 + d0 + threadIdx.x] =
            __float2half_rn(t[threadIdx.x][threadIdx.y + r * 8]);
    }
}

// ---------------- fp16 mma.sync gate GEMM ----------------
// BM=128, BN=128, BK=64 halves (128B rows), 3-stage cp.async, ldmatrix.
// 8 warps (2m x 4n), warp tile 64x32, m16n8k16.
__global__ __launch_bounds__(256)
void gates_gemm(const float* __restrict__ bz, const float* __restrict__ bfv,
                const float* __restrict__ bo) {
    extern __shared__ char dyn[];
    const uint32_t sbase = smem_u32(dyn);

    const int tid  = threadIdx.x;
    const int warp = tid >> 5, lane = tid & 31;
    const int gq = lane >> 2, q = lane & 3;
    const int wm0 = (warp & 1) * 64;
    const int wn0 = (warp >> 1) * 32;

    const int n0   = blockIdx.x * BN;      // n fast -> A reuse in L2 within a wave
    const int m0   = blockIdx.y * BM;
    const int gate = n0 >> 8;
    const int n0g  = n0 & 255;

    const float* bias = (gate == 0) ? bz : (gate == 1) ? bfv : bo;
    float* dst        = (gate == 0) ? g_z : (gate == 1) ? g_f : g_o;
    const __half* Wb  = g_wh + (size_t)gate * (DD * KTOT) + (size_t)n0g * KTOT;

    float acc[4][4][4];
    #pragma unroll
    for (int mt = 0; mt < 4; mt++)
        #pragma unroll
        for (int nt = 0; nt < 4; nt++)
            #pragma unroll
            for (int i = 0; i < 4; i++) acc[mt][nt][i] = 0.0f;

    // ---- producer: one BK=64-half stage (A 16KB + B 16KB) ----
    auto issue_stage = [&](int kb, int st) {
        const uint32_t abase = sbase + st * STAGE_BYTES;
        const uint32_t bbase = abase + A_BYTES;
        const int tap = kb >> 2;               // kb 0-3: tap0, 4-7: tap1
        const int d0  = (kb & 3) << 6;         // 64-half d-chunk within tap
        #pragma unroll
        for (int p = 0; p < 4; p++) {
            int idx = tid + p * 256;           // 1024 chunks of 16B (8 halves)
            int row = idx >> 3;
            int k4  = idx & 7;
            uint32_t sw = (uint32_t)(row << 7) + (uint32_t)((k4 ^ (row & 7)) << 4);
            // A
            int m = m0 + row;
            const __half* srcA;
            uint32_t nb = 16;
            if (tap == 0) {
                srcA = g_xh + (size_t)(m - 1) * DD + d0 + (k4 << 3);
                if ((m & (TT - 1)) == 0) { nb = 0; srcA = g_xh; }
            } else {
                srcA = g_xh + (size_t)m * DD + d0 + (k4 << 3);
            }
            cp_async16(abase + sw, srcA, nb);
            // B (n-major, k contiguous; k_total = kb*64 since tap*256+(kb&3)*64 = kb*64)
            const __half* srcB = Wb + (size_t)row * KTOT + (kb << 6) + (k4 << 3);
            cp_async16(bbase + sw, srcB, 16);
        }
    };

    // ---- consumer: 4 k16-steps per stage ----
    const int mi1 = (lane >> 3) & 1;
    const int mi2 = lane >> 4;
    const int rr  = lane & 7;
    auto compute = [&](int st) {
        const uint32_t ab = sbase + st * STAGE_BYTES;
        const uint32_t bb = ab + A_BYTES;
        #pragma unroll
        for (int ks = 0; ks < 4; ks++) {
            uint32_t af[4][4], bf[4][2];
            #pragma unroll
            for (int mt = 0; mt < 4; mt++) {
                int row = wm0 + mt * 16 + mi1 * 8 + rr;
                int k4  = ks * 2 + mi2;        // 16B col: k halves (ks*16 + mi2*8) .. +7
                uint32_t addr = ab + (row << 7) + ((k4 ^ (row & 7)) << 4);
                ldsm4(af[mt][0], af[mt][1], af[mt][2], af[mt][3], addr);
            }
            #pragma unroll
            for (int ntp = 0; ntp < 2; ntp++) {
                int row = wn0 + ntp * 16 + mi2 * 8 + rr;
                int k4  = ks * 2 + mi1;
                uint32_t addr = bb + (row << 7) + ((k4 ^ (row & 7)) << 4);
                uint32_t r0, r1, r2, r3;
                ldsm4(r0, r1, r2, r3, addr);
                bf[2*ntp][0] = r0;   bf[2*ntp][1] = r1;
                bf[2*ntp+1][0] = r2; bf[2*ntp+1][1] = r3;
            }
            #pragma unroll
            for (int mt = 0; mt < 4; mt++)
                #pragma unroll
                for (int nt = 0; nt < 4; nt++)
                    mma_f16(acc[mt][nt], af[mt], bf[nt]);
        }
    };

    // ---- pipeline ----
    issue_stage(0, 0); cp_commit();
    issue_stage(1, 1); cp_commit();

    int st = 0;
    for (int kb = 0; kb < NKB; kb++) {
        cp_wait<1>();
        __syncthreads();
        compute(st);
        if (kb + 2 < NKB) issue_stage(kb + 2, (kb + 2) % STAGES);
        cp_commit();
        st = (st + 1 == STAGES) ? 0 : st + 1;
    }

    // ---- epilogue: bias + activation, float2 stores ----
    #pragma unroll
    for (int mt = 0; mt < 4; mt++) {
        #pragma unroll
        for (int nt = 0; nt < 4; nt++) {
            #pragma unroll
            for (int h = 0; h < 2; h++) {
                int m  = m0 + wm0 + mt * 16 + gq + h * 8;
                int n  = n0g + wn0 + nt * 8 + q * 2;
                float v0 = acc[mt][nt][2*h]   + bias[n];
                float v1 = acc[mt][nt][2*h+1] + bias[n + 1];
                if (gate == 0) { v0 = tanhf(v0); v1 = tanhf(v1); }
                else { v0 = 1.0f / (1.0f + expf(-v0)); v1 = 1.0f / (1.0f + expf(-v1)); }
                *(float2*)(dst + (size_t)m * DD + n) = make_float2(v0, v1);
            }
        }
    }
}

// ---------------- segmented scan (round-7 scalar, proven fastest) ----------------
__global__ void seg_reduce() {
    int tid = blockIdx.x * 256 + threadIdx.x;   // 131072 threads: (b, s, d)
    int d = tid & 255;
    int s = (tid >> 8) & (NSEG - 1);
    int b = tid >> 14;
    size_t base = ((size_t)b * TT + (size_t)s * SEGL) * DD + d;
    float A = 1.0f, Bv = 0.0f;
    #pragma unroll 4
    for (int i = 0; i < SEGL; i++) {
        float f = g_f[base + (size_t)i * DD];
        float z = g_z[base + (size_t)i * DD];
        A  = f * A;
        Bv = f * Bv + (1.0f - f) * z;
    }
    int sidx = (b * NSEG + s) * DD + d;
    g_segA[sidx] = A;
    g_segB[sidx] = Bv;
}

__global__ void seg_carry() {
    int tid = blockIdx.x * 256 + threadIdx.x;   // 2048 threads: (b, d)
    int d = tid & 255;
    int b = tid >> 8;
    float c = 0.0f;
    for (int s = 0; s < NSEG; s++) {
        int idx = (b * NSEG + s) * DD + d;
        g_carry[idx] = c;
        c = g_segA[idx] * c + g_segB[idx];
    }
}

__global__ void seg_apply(float* __restrict__ out) {
    int tid = blockIdx.x * 256 + threadIdx.x;   // 131072 threads
    int d = tid & 255;
    int s = (tid >> 8) & (NSEG - 1);
    int b = tid >> 14;
    size_t base = ((size_t)b * TT + (size_t)s * SEGL) * DD + d;
    float c = g_carry[(b * NSEG + s) * DD + d];
    #pragma unroll 4
    for (int i = 0; i < SEGL; i++) {
        size_t idx = base + (size_t)i * DD;
        float f = g_f[idx];
        float z = g_z[idx];
        float o = g_o[idx];
        c = f * c + (1.0f - f) * z;
        out[idx] = o * c;
    }
}

// ---------------- launch ----------------
extern "C" void kernel_launch(void* const* d_in, const int* in_sizes, int n_in,
                              void* d_out, int out_size) {
    const float* x   = (const float*)d_in[0];
    const float* Wz  = (const float*)d_in[1];
    const float* Wf  = (const float*)d_in[2];
    const float* Wo  = (const float*)d_in[3];
    const float* bz  = (const float*)d_in[4];
    const float* bfv = (const float*)d_in[5];
    const float* bo  = (const float*)d_in[6];
    float* out = (float*)d_out;

    cudaFuncSetAttribute(gates_gemm, cudaFuncAttributeMaxDynamicSharedMemorySize, DYN_SMEM);

    cvt_x<<<(MTOT * DD / 4) / 256, 256>>>(x);
    trans_w<<<dim3(64, 2, 3), dim3(32, 8)>>>(Wz, Wf, Wo);
    gates_gemm<<<dim3(768 / BN, MTOT / BM), 256, DYN_SMEM>>>(bz, bfv, bo);
    seg_reduce<<<(BB * NSEG * DD) / 256, 256>>>();
    seg_carry<<<(BB * DD) / 256, 256>>>();
    seg_apply<<<(BB * NSEG * DD) / 256, 256>>>(out);
}